// round 16
// baseline (speedup 1.0000x reference)
#include <cuda_runtime.h>
#include <math_constants.h>

// Morphological opening (10x10 min then 10x10 max, SAME pad lo=4/hi=5),
// NHWC [16,512,512,8] f32. Fused kernel, vertical-first, streaming van Herk,
// H-min/H-max chained in registers (no E intermediate).
// vs round 15: V2 split into 2 e-segments (256 tasks -> all threads busy,
// half the stage critical path), output written with __stwt (streaming,
// don't pollute L2 halo working set). Core stages unchanged.

#define H_  512
#define W_  512
#define TH  16
#define TW  32
#define NT  256

#define NE  25            // outputs per column (TH + 9)
#define NCB 50            // B cols (TW + 18)
#define BQ  (NCB * 4)     // 200 fused (col, f2-quarter) B columns
#define FQ  (TW * 4)      // 128

#define F_OFF (BQ * NE)               // 5000 f2
#define SMEM_F2 (F_OFF + FQ * NE)     // 8200 f2
#define SMEM_BYTES (SMEM_F2 * 8)      // 65,600 -> 3 blocks/SM

__device__ __forceinline__ float2 mn2(float2 a, float2 b) {
    return make_float2(fminf(a.x,b.x), fminf(a.y,b.y));
}
__device__ __forceinline__ float2 mx2(float2 a, float2 b) {
    return make_float2(fmaxf(a.x,b.x), fmaxf(a.y,b.y));
}
template<bool MN>
__device__ __forceinline__ float2 op2(float2 a, float2 b) { return MN ? mn2(a,b) : mx2(a,b); }

// Streaming van Herk: out[i] = OP(in[i..i+9]) for i in [0,NOUT).
template<bool MN, int NOUT, class L, class S>
__device__ __forceinline__ void svh(L ld, S st) {
    constexpr int NIN  = NOUT + 9;
    constexpr int NBLK = (NOUT + 8) / 9;
    float2 s[9];
    #pragma unroll
    for (int t = 0; t < 9; t++) s[t] = ld(t);
    #pragma unroll
    for (int j = 7; j >= 0; j--) s[j] = op2<MN>(s[j], s[j+1]);
    #pragma unroll
    for (int m = 0; m < NBLK; m++) {
        const int base = 9 * m;
        const int ycnt = (NIN - 9*(m+1) < 9) ? (NIN - 9*(m+1)) : 9;
        float2 y[9];
        #pragma unroll
        for (int t = 0; t < 9; t++) if (t < ycnt) y[t] = ld(9*(m+1) + t);
        float2 pr = y[0];
        st(base, op2<MN>(s[0], pr));
        #pragma unroll
        for (int r = 1; r < 9; r++) {
            if (base + r < NOUT) {
                pr = op2<MN>(pr, y[r]);
                st(base + r, op2<MN>(s[r], pr));
            }
        }
        if (m + 1 < NBLK) {
            #pragma unroll
            for (int j = 7; j >= 0; j--) y[j] = op2<MN>(y[j], y[j+1]);
            #pragma unroll
            for (int t = 0; t < 9; t++) s[t] = y[t];
        }
    }
}

__global__ __launch_bounds__(NT, 3)
void opening_kernel(const float2* __restrict__ in2, float2* __restrict__ out2) {
    extern __shared__ float2 sm[];
    float2* Bs = sm;            // B[cQ][e], cQ = cb*4 + q, stride NE
    float2* Fs = sm + F_OFF;    // F[cQ''][e]

    const int b   = blockIdx.z;
    const int gh0 = blockIdx.y * TH;
    const int gw0 = blockIdx.x * TW;
    const int tid = threadIdx.x;

    const size_t chanBase = (size_t)b * ((size_t)H_ * W_ * 4);  // f2 units
    const float2 INF2  = make_float2( CUDART_INF_F,  CUDART_INF_F);
    const float2 NINF2 = make_float2(-CUDART_INF_F, -CUDART_INF_F);

    // ---- V1: vertical min streamed from gmem (coalesced). 200 tasks. ----
    if (tid < BQ) {
        int cQ = tid, cb = cQ >> 2, q = cQ & 3;
        int gx = gw0 + cb - 8;
        float2* qB = Bs + cQ * NE;
        if ((unsigned)gx >= W_) {
            #pragma unroll
            for (int i = 0; i < NE; i++) qB[i] = INF2;
        } else {
            const float2* src = in2 + chanBase + (size_t)gx * 4 + q;
            int gy0 = gh0 - 8;
            auto st = [&](int i, float2 v) { qB[i] = v; };
            if (gh0 != 0 && gh0 != (H_ - TH)) {
                auto ld = [&](int t) { return src[(size_t)(gy0 + t) * (W_ * 4)]; };
                svh<true, NE>(ld, st);
            } else {
                auto ld = [&](int t) {
                    int gy = gy0 + t; float2 v = INF2;
                    if ((unsigned)gy < H_) v = src[(size_t)gy * (W_ * 4)];
                    return v;
                };
                svh<true, NE>(ld, st);
            }
        }
    }
    __syncthreads();

    // ---- Hfused: B -> F, eroded E chained in registers. 200 tasks. ----
    if (tid < 200) {
        int e    = tid % 25;
        int t2   = tid / 25;       // 0..7
        int q    = t2 & 3;
        int half = t2 >> 2;
        int cB0  = half * 16;
        const float2* pB = Bs + (cB0 * 4 + q) * NE + e;  // B col step 4*NE
        float2*       pF = Fs + (cB0 * 4 + q) * NE + e;  // F col = cB0 + j
        bool rowOK   = ((unsigned)(gh0 + e - 4) < H_);
        int  colBase = gw0 + cB0 - 4;                    // E i=0 global col
        bool needMask = !(rowOK && colBase >= 0 && colBase + 24 < W_);

        float2 sB[9], yB[9], sE[9], eb[9];
        #pragma unroll
        for (int t = 0; t < 9; t++) sB[t] = pB[t * (4 * NE)];
        #pragma unroll
        for (int j = 7; j >= 0; j--) sB[j] = mn2(sB[j], sB[j+1]);

        // --- produce E[0..8] ---
        #pragma unroll
        for (int t = 0; t < 9; t++) yB[t] = pB[(9 + t) * (4 * NE)];
        {
            float2 pr = yB[0];
            eb[0] = mn2(sB[0], pr);
            #pragma unroll
            for (int r = 1; r < 9; r++) { pr = mn2(pr, yB[r]); eb[r] = mn2(sB[r], pr); }
        }
        if (needMask) {
            #pragma unroll
            for (int r = 0; r < 9; r++)
                if (!rowOK || (unsigned)(colBase + r) >= W_) eb[r] = NINF2;
        }
        #pragma unroll
        for (int t = 0; t < 9; t++) sE[t] = eb[t];
        #pragma unroll
        for (int j = 7; j >= 0; j--) sE[j] = mx2(sE[j], sE[j+1]);
        #pragma unroll
        for (int j = 7; j >= 0; j--) yB[j] = mn2(yB[j], yB[j+1]);
        #pragma unroll
        for (int t = 0; t < 9; t++) sB[t] = yB[t];

        // --- produce E[9..17], emit F[0..8] ---
        #pragma unroll
        for (int t = 0; t < 9; t++) yB[t] = pB[(18 + t) * (4 * NE)];
        {
            float2 pr = yB[0];
            eb[0] = mn2(sB[0], pr);
            #pragma unroll
            for (int r = 1; r < 9; r++) { pr = mn2(pr, yB[r]); eb[r] = mn2(sB[r], pr); }
        }
        if (needMask) {
            #pragma unroll
            for (int r = 0; r < 9; r++)
                if (!rowOK || (unsigned)(colBase + 9 + r) >= W_) eb[r] = NINF2;
        }
        {
            float2 pr = eb[0];
            pF[0] = mx2(sE[0], pr);
            #pragma unroll
            for (int r = 1; r < 9; r++) { pr = mx2(pr, eb[r]); pF[r * (4 * NE)] = mx2(sE[r], pr); }
        }
        #pragma unroll
        for (int j = 7; j >= 0; j--) eb[j] = mx2(eb[j], eb[j+1]);
        #pragma unroll
        for (int t = 0; t < 9; t++) sE[t] = eb[t];
        #pragma unroll
        for (int j = 7; j >= 0; j--) yB[j] = mn2(yB[j], yB[j+1]);
        #pragma unroll
        for (int t = 0; t < 9; t++) sB[t] = yB[t];

        // --- produce E[18..24] (7), emit F[9..15] (7) ---
        #pragma unroll
        for (int t = 0; t < 7; t++) yB[t] = pB[(27 + t) * (4 * NE)];
        {
            float2 pr = yB[0];
            eb[0] = mn2(sB[0], pr);
            #pragma unroll
            for (int r = 1; r < 7; r++) { pr = mn2(pr, yB[r]); eb[r] = mn2(sB[r], pr); }
        }
        if (needMask) {
            #pragma unroll
            for (int r = 0; r < 7; r++)
                if (!rowOK || (unsigned)(colBase + 18 + r) >= W_) eb[r] = NINF2;
        }
        {
            float2 pr = eb[0];
            pF[9 * (4 * NE)] = mx2(sE[0], pr);
            #pragma unroll
            for (int r = 1; r < 7; r++) { pr = mx2(pr, eb[r]); pF[(9 + r) * (4 * NE)] = mx2(sE[r], pr); }
        }
    }
    __syncthreads();

    // ---- V2: vertical max F -> gmem (coalesced, streaming). 256 tasks. ----
    // seg0: rows 0-7 from F[0..16]; seg1: rows 8-15 from F[8..24].
    {
        int cQ  = tid & 127;
        int seg = tid >> 7;
        const float2* pF = Fs + cQ * NE + seg * 8;   // stride 1 along e
        float2* qo = out2 + chanBase + ((size_t)(gh0 + seg * 8) * W_ + gw0) * 4 + cQ;
        auto ld = [&](int t) { return pF[t]; };
        auto st = [&](int i, float2 v) { __stwt(&qo[(size_t)i * (W_ * 4)], v); };
        svh<false, 8>(ld, st);
    }
}

extern "C" void kernel_launch(void* const* d_in, const int* in_sizes, int n_in,
                              void* d_out, int out_size) {
    const float2* in  = (const float2*)d_in[0];
    float2* out = (float2*)d_out;

    cudaFuncSetAttribute(opening_kernel,
                         cudaFuncAttributeMaxDynamicSharedMemorySize, SMEM_BYTES);

    dim3 grid(W_ / TW, H_ / TH, 16);
    opening_kernel<<<grid, NT, SMEM_BYTES>>>(in, out);
}